// round 2
// baseline (speedup 1.0000x reference)
#include <cuda_runtime.h>

// AnnularDilatedKNN: B=4, N=4096, C=64, SAMPLE=16, DILATED_RATE=2 -> NSAMPLE=32, K_out=16
// radius^2 = 256.
//
// R1 change: query kernel vectorized 4x — each lane evaluates 4 consecutive
// candidates via float4 SoA loads (128 candidates/iteration, max 32 trips vs 128).
// Ordered hit extraction: 4 sub-ballots; position of candidate (lane l, sub j)
//   = cnt + sum_j popc(ballot_j & lanemask_lt) + (# earlier set bits in own nibble).
// Per-candidate arithmetic is unchanged from the rel_err=0.0 R0 kernel.

#define NB   4
#define NP   4096
#define KOUT 16

__device__ float g_xs[NB * NP];
__device__ float g_ys[NB * NP];
__device__ float g_zs[NB * NP];
__device__ float g_sq[NB * NP];
__device__ int   g_ids[NB * NP * KOUT];

__global__ __launch_bounds__(256) void prep_kernel(const float* __restrict__ xyz) {
    const int i = blockIdx.x * 256 + threadIdx.x;
    if (i >= NB * NP) return;
    const float x = xyz[3 * i + 0];
    const float y = xyz[3 * i + 1];
    const float z = xyz[3 * i + 2];
    g_xs[i] = x;
    g_ys[i] = y;
    g_zs[i] = z;
    // jnp.sum(xyz*xyz, -1): left-to-right, separately rounded products (no fma).
    g_sq[i] = __fadd_rn(__fadd_rn(__fmul_rn(x, x), __fmul_rn(y, y)), __fmul_rn(z, z));
}

__global__ __launch_bounds__(256) void query_kernel() {
    __shared__ int sh_hits[8][32];
    const int warp = threadIdx.x >> 5;
    const int lane = threadIdx.x & 31;
    const int q = (blockIdx.x << 3) + warp;      // global query id, 0..16383
    const int b = q >> 12;
    const int n = q & (NP - 1);
    const int bb = b << 12;

    const float xn  = g_xs[bb + n];
    const float yn  = g_ys[bb + n];
    const float zn  = g_zs[bb + n];
    const float sqn = g_sq[bb + n];

    const float4* __restrict__ X  = reinterpret_cast<const float4*>(g_xs) + (bb >> 2);
    const float4* __restrict__ Y  = reinterpret_cast<const float4*>(g_ys) + (bb >> 2);
    const float4* __restrict__ Z  = reinterpret_cast<const float4*>(g_zs) + (bb >> 2);
    const float4* __restrict__ SQ = reinterpret_cast<const float4*>(g_sq) + (bb >> 2);

    int cnt = 0;
    const unsigned lmask = (1u << lane) - 1u;

    for (int base = 0; base < NP; base += 128) {
        const int fi = (base >> 2) + lane;       // lane's float4 index: candidates base+4*lane..+3
        const float4 x4 = X[fi];
        const float4 y4 = Y[fi];
        const float4 z4 = Z[fi];
        const float4 s4 = SQ[fi];

        unsigned nib = 0;
        {   // identical per-candidate arithmetic to R0 (rel_err = 0 verified)
            float dot, d2;
            dot = fmaf(zn, z4.x, fmaf(yn, y4.x, __fmul_rn(xn, x4.x)));
            d2  = __fsub_rn(__fadd_rn(sqn, s4.x), __fmul_rn(2.0f, dot));
            if (d2 < 256.0f) nib |= 1u;
            dot = fmaf(zn, z4.y, fmaf(yn, y4.y, __fmul_rn(xn, x4.y)));
            d2  = __fsub_rn(__fadd_rn(sqn, s4.y), __fmul_rn(2.0f, dot));
            if (d2 < 256.0f) nib |= 2u;
            dot = fmaf(zn, z4.z, fmaf(yn, y4.z, __fmul_rn(xn, x4.z)));
            d2  = __fsub_rn(__fadd_rn(sqn, s4.z), __fmul_rn(2.0f, dot));
            if (d2 < 256.0f) nib |= 4u;
            dot = fmaf(zn, z4.w, fmaf(yn, y4.w, __fmul_rn(xn, x4.w)));
            d2  = __fsub_rn(__fadd_rn(sqn, s4.w), __fmul_rn(2.0f, dot));
            if (d2 < 256.0f) nib |= 8u;
        }

        const unsigned b0 = __ballot_sync(0xffffffffu, nib & 1u);
        const unsigned b1 = __ballot_sync(0xffffffffu, nib & 2u);
        const unsigned b2 = __ballot_sync(0xffffffffu, nib & 4u);
        const unsigned b3 = __ballot_sync(0xffffffffu, nib & 8u);

        if (nib) {
            int p = cnt + __popc(b0 & lmask) + __popc(b1 & lmask)
                        + __popc(b2 & lmask) + __popc(b3 & lmask);
            const int c0 = base + (lane << 2);
            if (nib & 1u) { if (p < 31) sh_hits[warp][p] = c0;     ++p; }
            if (nib & 2u) { if (p < 31) sh_hits[warp][p] = c0 + 1; ++p; }
            if (nib & 4u) { if (p < 31) sh_hits[warp][p] = c0 + 2; ++p; }
            if (nib & 8u) { if (p < 31) sh_hits[warp][p] = c0 + 3; ++p; }
        }

        cnt += __popc(b0) + __popc(b1) + __popc(b2) + __popc(b3);
        if (cnt >= 31) break;                    // uniform: cnt derived from ballots
    }
    __syncwarp();

    if (lane < KOUT) {
        const int h0 = sh_hits[warp][0];         // center = first (smallest-index) hit
        int v = h0;                              // (self-hit guarantees cnt >= 1)
        if (lane > 0) {
            const int j = lane + 15;             // annular region: hits 16..30
            if (j < cnt) v = sh_hits[warp][j];   // else padded with center
        }
        g_ids[(q << 4) + lane] = v;
    }
}

__global__ __launch_bounds__(256) void gather_kernel(const float* __restrict__ xyz,
                                                     const float* __restrict__ feat,
                                                     float* __restrict__ out) {
    const int idx = blockIdx.x * 256 + threadIdx.x;   // 0..262143 = (b, n, k)
    const int id  = g_ids[idx];
    const int k   = idx & 15;
    const int n   = (idx >> 4) & (NP - 1);
    const int b   = idx >> 16;
    const int nk  = (n << 4) | k;                     // fastest in k -> coalesced writes

    // dilated_xyz: [B, 3, N, K]
    const float* src = xyz + ((b << 12) + id) * 3;
    float* oxyz = out + ((b * 3) << 16) + nk;
    oxyz[0]         = src[0];
    oxyz[1 << 16]   = src[1];
    oxyz[2 << 16]   = src[2];

    // dilated_feature: [B, 64, N, K] starting after the xyz block
    const float4* f4 = reinterpret_cast<const float4*>(feat) + (((b << 12) + id) << 4);
    float* ofeat = out + ((NB * 3) << 16) + ((b * 64) << 16) + nk;
    #pragma unroll
    for (int c4 = 0; c4 < 16; ++c4) {
        const float4 v = f4[c4];
        ofeat[((c4 * 4 + 0) << 16)] = v.x;
        ofeat[((c4 * 4 + 1) << 16)] = v.y;
        ofeat[((c4 * 4 + 2) << 16)] = v.z;
        ofeat[((c4 * 4 + 3) << 16)] = v.w;
    }
}

extern "C" void kernel_launch(void* const* d_in, const int* in_sizes, int n_in,
                              void* d_out, int out_size) {
    const float* xyz  = (const float*)d_in[0];
    const float* feat = (const float*)d_in[1];
    float* out = (float*)d_out;
    prep_kernel<<<(NB * NP + 255) / 256, 256>>>(xyz);
    query_kernel<<<(NB * NP) / 8, 256>>>();
    gather_kernel<<<(NB * NP * KOUT) / 256, 256>>>(xyz, feat, out);
}

// round 3
// speedup vs baseline: 1.3680x; 1.3680x over previous
#include <cuda_runtime.h>

// AnnularDilatedKNN: B=4, N=4096, C=64, SAMPLE=16, DILATED_RATE=2 -> NSAMPLE=32, K_out=16
// radius^2 = 256.
//
// R2: query kernel reworked around the measured-latency model:
//  - per-block SMEM staging of the batch SoA (64KB dynamic smem) -> 29cyc LDS,
//    no L1/L2 capacity thrash (working set was ~256KB across resident blocks)
//  - 2-stage software pipeline: prefetch chunk i+1 into registers while chunk i
//    is evaluated, removing load latency from the serial per-iteration chain
//  - extraction bookkeeping identical to R1 (rel_err=0.0 verified), arithmetic
//    identical to R0 (rel_err=0.0 verified).

#define NB   4
#define NP   4096
#define KOUT 16

__device__ float g_xs[NB * NP];
__device__ float g_ys[NB * NP];
__device__ float g_zs[NB * NP];
__device__ float g_sq[NB * NP];
__device__ int   g_ids[NB * NP * KOUT];

__global__ __launch_bounds__(256) void prep_kernel(const float* __restrict__ xyz) {
    const int i = blockIdx.x * 256 + threadIdx.x;
    if (i >= NB * NP) return;
    const float x = xyz[3 * i + 0];
    const float y = xyz[3 * i + 1];
    const float z = xyz[3 * i + 2];
    g_xs[i] = x;
    g_ys[i] = y;
    g_zs[i] = z;
    // jnp.sum(xyz*xyz, -1): left-to-right, separately rounded products (no fma).
    g_sq[i] = __fadd_rn(__fadd_rn(__fmul_rn(x, x), __fmul_rn(y, y)), __fmul_rn(z, z));
}

// nib evaluation: byte-identical arithmetic to the verified R0/R1 kernels.
__device__ __forceinline__ unsigned eval_nib(float xn, float yn, float zn, float sqn,
                                             float4 x4, float4 y4, float4 z4, float4 s4) {
    unsigned nib = 0;
    float dot, d2;
    dot = fmaf(zn, z4.x, fmaf(yn, y4.x, __fmul_rn(xn, x4.x)));
    d2  = __fsub_rn(__fadd_rn(sqn, s4.x), __fmul_rn(2.0f, dot));
    if (d2 < 256.0f) nib |= 1u;
    dot = fmaf(zn, z4.y, fmaf(yn, y4.y, __fmul_rn(xn, x4.y)));
    d2  = __fsub_rn(__fadd_rn(sqn, s4.y), __fmul_rn(2.0f, dot));
    if (d2 < 256.0f) nib |= 2u;
    dot = fmaf(zn, z4.z, fmaf(yn, y4.z, __fmul_rn(xn, x4.z)));
    d2  = __fsub_rn(__fadd_rn(sqn, s4.z), __fmul_rn(2.0f, dot));
    if (d2 < 256.0f) nib |= 4u;
    dot = fmaf(zn, z4.w, fmaf(yn, y4.w, __fmul_rn(xn, x4.w)));
    d2  = __fsub_rn(__fadd_rn(sqn, s4.w), __fmul_rn(2.0f, dot));
    if (d2 < 256.0f) nib |= 8u;
    return nib;
}

__global__ __launch_bounds__(256) void query_kernel() {
    extern __shared__ float sm[];
    float* sx  = sm;
    float* sy  = sm + NP;
    float* sz  = sm + 2 * NP;
    float* ssq = sm + 3 * NP;
    __shared__ int sh_hits[8][32];

    const int warp = threadIdx.x >> 5;
    const int lane = threadIdx.x & 31;
    const int q = (blockIdx.x << 3) + warp;      // global query id, 0..16383
    const int b = q >> 12;                        // all 8 warps of a block share b
    const int n = q & (NP - 1);
    const int bb = b << 12;

    // Stage the whole batch SoA (64KB) into shared memory, float4-wide.
    {
        const float4* gx = reinterpret_cast<const float4*>(g_xs + bb);
        const float4* gy = reinterpret_cast<const float4*>(g_ys + bb);
        const float4* gz = reinterpret_cast<const float4*>(g_zs + bb);
        const float4* gs = reinterpret_cast<const float4*>(g_sq + bb);
        float4* tx = reinterpret_cast<float4*>(sx);
        float4* ty = reinterpret_cast<float4*>(sy);
        float4* tz = reinterpret_cast<float4*>(sz);
        float4* ts = reinterpret_cast<float4*>(ssq);
        #pragma unroll
        for (int i = threadIdx.x; i < NP / 4; i += 256) {
            tx[i] = gx[i];
            ty[i] = gy[i];
            tz[i] = gz[i];
            ts[i] = gs[i];
        }
    }
    __syncthreads();

    const float xn  = sx[n];
    const float yn  = sy[n];
    const float zn  = sz[n];
    const float sqn = ssq[n];

    const float4* X  = reinterpret_cast<const float4*>(sx);
    const float4* Y  = reinterpret_cast<const float4*>(sy);
    const float4* Z  = reinterpret_cast<const float4*>(sz);
    const float4* SQ = reinterpret_cast<const float4*>(ssq);

    int cnt = 0;
    const unsigned lmask = (1u << lane) - 1u;

    // 2-stage pipeline: current chunk in (x4..s4), prefetch next into (px..ps).
    int fi = lane;
    float4 x4 = X[fi], y4 = Y[fi], z4 = Z[fi], s4 = SQ[fi];

    for (int base = 0; base < NP; ) {
        const int nbase = base + 128;
        float4 px, py, pz, ps;
        if (nbase < NP) {
            const int nfi = (nbase >> 2) + lane;
            px = X[nfi]; py = Y[nfi]; pz = Z[nfi]; ps = SQ[nfi];
        }

        const unsigned nib = eval_nib(xn, yn, zn, sqn, x4, y4, z4, s4);

        const unsigned b0 = __ballot_sync(0xffffffffu, nib & 1u);
        const unsigned b1 = __ballot_sync(0xffffffffu, nib & 2u);
        const unsigned b2 = __ballot_sync(0xffffffffu, nib & 4u);
        const unsigned b3 = __ballot_sync(0xffffffffu, nib & 8u);

        if (nib) {
            int p = cnt + __popc(b0 & lmask) + __popc(b1 & lmask)
                        + __popc(b2 & lmask) + __popc(b3 & lmask);
            const int c0 = base + (lane << 2);
            if (nib & 1u) { if (p < 31) sh_hits[warp][p] = c0;     ++p; }
            if (nib & 2u) { if (p < 31) sh_hits[warp][p] = c0 + 1; ++p; }
            if (nib & 4u) { if (p < 31) sh_hits[warp][p] = c0 + 2; ++p; }
            if (nib & 8u) { if (p < 31) sh_hits[warp][p] = c0 + 3; ++p; }
        }

        cnt += __popc(b0) + __popc(b1) + __popc(b2) + __popc(b3);
        if (cnt >= 31) break;                    // uniform: cnt derived from ballots
        base = nbase;
        if (base >= NP) break;
        x4 = px; y4 = py; z4 = pz; s4 = ps;
    }
    __syncwarp();

    if (lane < KOUT) {
        const int h0 = sh_hits[warp][0];         // center = first (smallest-index) hit
        int v = h0;                              // (self-hit guarantees cnt >= 1)
        if (lane > 0) {
            const int j = lane + 15;             // annular region: hits 16..30
            if (j < cnt) v = sh_hits[warp][j];   // else padded with center
        }
        g_ids[(q << 4) + lane] = v;
    }
}

__global__ __launch_bounds__(256) void gather_kernel(const float* __restrict__ xyz,
                                                     const float* __restrict__ feat,
                                                     float* __restrict__ out) {
    const int idx = blockIdx.x * 256 + threadIdx.x;   // 0..262143 = (b, n, k)
    const int id  = g_ids[idx];
    const int k   = idx & 15;
    const int n   = (idx >> 4) & (NP - 1);
    const int b   = idx >> 16;
    const int nk  = (n << 4) | k;                     // fastest in k -> coalesced writes

    // dilated_xyz: [B, 3, N, K]
    const float* src = xyz + ((b << 12) + id) * 3;
    float* oxyz = out + ((b * 3) << 16) + nk;
    oxyz[0]         = src[0];
    oxyz[1 << 16]   = src[1];
    oxyz[2 << 16]   = src[2];

    // dilated_feature: [B, 64, N, K] starting after the xyz block
    const float4* f4 = reinterpret_cast<const float4*>(feat) + (((b << 12) + id) << 4);
    float* ofeat = out + ((NB * 3) << 16) + ((b * 64) << 16) + nk;
    #pragma unroll
    for (int c4 = 0; c4 < 16; ++c4) {
        const float4 v = f4[c4];
        ofeat[((c4 * 4 + 0) << 16)] = v.x;
        ofeat[((c4 * 4 + 1) << 16)] = v.y;
        ofeat[((c4 * 4 + 2) << 16)] = v.z;
        ofeat[((c4 * 4 + 3) << 16)] = v.w;
    }
}

extern "C" void kernel_launch(void* const* d_in, const int* in_sizes, int n_in,
                              void* d_out, int out_size) {
    const float* xyz  = (const float*)d_in[0];
    const float* feat = (const float*)d_in[1];
    float* out = (float*)d_out;

    static bool attr_done = false;
    if (!attr_done) {
        cudaFuncSetAttribute(query_kernel,
                             cudaFuncAttributeMaxDynamicSharedMemorySize, 4 * NP * 4);
        attr_done = true;
    }

    prep_kernel<<<(NB * NP + 255) / 256, 256>>>(xyz);
    query_kernel<<<(NB * NP) / 8, 256, 4 * NP * 4>>>();
    gather_kernel<<<(NB * NP * KOUT) / 256, 256>>>(xyz, feat, out);
}